// round 16
// baseline (speedup 1.0000x reference)
#include <cuda_runtime.h>
#include <cuda_bf16.h>
#include <cstdint>

#define NN 60000
#define CC 128
#define EE 600000
#define HID 32

// TF32 operand rounding (round-to-nearest)
__device__ __forceinline__ float tf32r(float x) {
    uint32_t u;
    asm("cvt.rna.tf32.f32 %0, %1;" : "=r"(u) : "f"(x));
    return __uint_as_float(u);
}

// ---------------- scratch (__device__ globals; no allocations) ----------------
__device__ __nv_bfloat162 g_hb[(size_t)NN * (CC / 2)];  // state @ Wg, bf16
__device__ int   g_counts[NN];             // in-degree (edges only)
__device__ int   g_offsets[NN + 1];        // CSR offsets by dst
__device__ int   g_cursor[NN];
__device__ float g_dinv[NN];               // 1/sqrt(deg+1)
__device__ int   g_src32[EE];
__device__ int   g_dst32[EE];
__device__ int   g_csr[EE];                // src per CSR slot
__device__ float g_conc[NN];
__device__ float g_sum;
__device__ int   g_is64;

// ---------------- K0: init (dtype detect, zero counts + sum) ----------------
__global__ void k_init(const void* edge) {
    int i = blockIdx.x * blockDim.x + threadIdx.x;
    if (i == 0) {
        const unsigned* w = (const unsigned*)edge;
        int is64 = 1;
        for (int k = 0; k < 32; k++) {
            if (w[2 * k + 1] != 0u) { is64 = 0; break; }
        }
        g_is64 = is64;
        g_sum = 0.0f;
    }
    for (int j = i; j < NN; j += gridDim.x * blockDim.x) g_counts[j] = 0;
}

// ---------------- K1: convert indices + dst histogram ----------------
__global__ void k_hist(const void* edge) {
    const int is64 = g_is64;
    for (int e = blockIdx.x * blockDim.x + threadIdx.x; e < EE;
         e += gridDim.x * blockDim.x) {
        int s, d;
        if (is64) {
            const long long* p = (const long long*)edge;
            s = (int)p[e]; d = (int)p[(size_t)EE + e];
        } else {
            const int* p = (const int*)edge;
            s = p[e]; d = p[(size_t)EE + e];
        }
        if ((unsigned)s >= NN) s = 0;   // safety clamp
        if ((unsigned)d >= NN) d = 0;
        g_src32[e] = s;
        g_dst32[e] = d;
        atomicAdd(&g_counts[d], 1);
    }
}

// ---------------- K2: single-block full scan + dinv + cursor init ------------
__global__ __launch_bounds__(1024) void k_scan() {
    __shared__ int ss[1024];
    const int t = threadIdx.x;
    const int per = (NN + 1023) / 1024;     // 59
    const int beg = t * per;
    const int end = min(beg + per, NN);

    int s = 0;
    for (int i = beg; i < end; i++) s += g_counts[i];
    ss[t] = s;
    __syncthreads();
    for (int o = 1; o < 1024; o <<= 1) {
        int v = (t >= o) ? ss[t - o] : 0;
        __syncthreads();
        ss[t] += v;
        __syncthreads();
    }
    int run = ss[t] - s;    // exclusive prefix of this thread's chunk
    for (int i = beg; i < end; i++) {
        int c = g_counts[i];
        g_offsets[i] = run;
        g_cursor[i] = run;
        g_dinv[i] = rsqrtf((float)(c + 1));
        run += c;
    }
    if (t == 1023) g_offsets[NN] = ss[1023];   // == EE
}

// ---------------- K3: scatter edges into CSR ----------------
__global__ void k_fill() {
    for (int e = blockIdx.x * blockDim.x + threadIdx.x; e < EE;
         e += gridDim.x * blockDim.x) {
        int d = g_dst32[e];
        int pos = atomicAdd(&g_cursor[d], 1);
        g_csr[pos] = g_src32[e];
    }
}

// ---------------- K4: SGEMM  g_hb = bf16(state @ Wg) ----------------
__global__ __launch_bounds__(256) void k_gemm(const float* __restrict__ A,
                                              const float* __restrict__ B) {
    __shared__ float sA[2][8][132];   // [k][row], padded
    __shared__ float sB[2][8][128];   // [k][col]
    const int tid = threadIdx.x;
    const int tx = tid & 15, ty = tid >> 4;        // 16x16 thread grid, 8x8 tiles
    const int row0 = blockIdx.x * 128;
    const int lr = tid >> 1, lk4 = (tid & 1) * 4;  // A load mapping
    const int bk = tid >> 5, bn4 = tid & 31;       // B load mapping

    float acc[8][8];
    #pragma unroll
    for (int i = 0; i < 8; i++)
        #pragma unroll
        for (int j = 0; j < 8; j++) acc[i][j] = 0.f;

    auto load = [&](int buf, int kc) {
        float4 va = make_float4(0.f, 0.f, 0.f, 0.f);
        int r = row0 + lr;
        if (r < NN) va = *(const float4*)(A + (size_t)r * CC + kc * 8 + lk4);
        sA[buf][lk4 + 0][lr] = tf32r(va.x);
        sA[buf][lk4 + 1][lr] = tf32r(va.y);
        sA[buf][lk4 + 2][lr] = tf32r(va.z);
        sA[buf][lk4 + 3][lr] = tf32r(va.w);
        float4 vb = *(const float4*)(B + (size_t)(kc * 8 + bk) * CC + bn4 * 4);
        sB[buf][bk][bn4 * 4 + 0] = tf32r(vb.x);
        sB[buf][bk][bn4 * 4 + 1] = tf32r(vb.y);
        sB[buf][bk][bn4 * 4 + 2] = tf32r(vb.z);
        sB[buf][bk][bn4 * 4 + 3] = tf32r(vb.w);
    };

    load(0, 0);
    __syncthreads();

    #pragma unroll
    for (int kc = 0; kc < 16; kc++) {
        const int buf = kc & 1;
        if (kc < 15) load(buf ^ 1, kc + 1);
        #pragma unroll
        for (int k = 0; k < 8; k++) {
            float4 a0 = *(const float4*)&sA[buf][k][ty * 8];
            float4 a1 = *(const float4*)&sA[buf][k][ty * 8 + 4];
            float4 b0 = *(const float4*)&sB[buf][k][tx * 8];
            float4 b1 = *(const float4*)&sB[buf][k][tx * 8 + 4];
            float av[8] = {a0.x, a0.y, a0.z, a0.w, a1.x, a1.y, a1.z, a1.w};
            float bv[8] = {b0.x, b0.y, b0.z, b0.w, b1.x, b1.y, b1.z, b1.w};
            #pragma unroll
            for (int i = 0; i < 8; i++)
                #pragma unroll
                for (int j = 0; j < 8; j++)
                    acc[i][j] = fmaf(av[i], bv[j], acc[i][j]);
        }
        __syncthreads();
    }

    // epilogue: 8 fp32 -> 4 bf162 per row slice, one 16B store
    #pragma unroll
    for (int i = 0; i < 8; i++) {
        int r = row0 + ty * 8 + i;
        if (r < NN) {
            __nv_bfloat162 p0 = __floats2bfloat162_rn(acc[i][0], acc[i][1]);
            __nv_bfloat162 p1 = __floats2bfloat162_rn(acc[i][2], acc[i][3]);
            __nv_bfloat162 p2 = __floats2bfloat162_rn(acc[i][4], acc[i][5]);
            __nv_bfloat162 p3 = __floats2bfloat162_rn(acc[i][6], acc[i][7]);
            uint4 o;
            o.x = *(unsigned*)&p0; o.y = *(unsigned*)&p1;
            o.z = *(unsigned*)&p2; o.w = *(unsigned*)&p3;
            *(uint4*)(g_hb + (size_t)r * (CC / 2) + tx * 4) = o;
        }
    }
}

// ---------------- K5: warp-per-node gather + fused MLP + partial reduce ------
__global__ __launch_bounds__(256) void k_agg_mlp(
    const float* __restrict__ state, const float* __restrict__ bg,
    const float* __restrict__ W1, const float* __restrict__ b1,
    const float* __restrict__ W2, const float* __restrict__ b2,
    const float* __restrict__ W3, const float* __restrict__ b3) {
    __shared__ float sW1[CC * HID];    // [c][j], tf32-rounded
    __shared__ float sW2[HID * HID];   // [k][j], tf32-rounded
    __shared__ float sW3[HID];
    __shared__ float sb1[HID], sb2[HID];
    __shared__ float sbg[CC];
    __shared__ float sx[8][CC];
    __shared__ float spart[8];

    const int tid = threadIdx.x;
    for (int i = tid; i < CC * HID; i += 256) sW1[i] = tf32r(W1[i]);
    for (int i = tid; i < HID * HID; i += 256) sW2[i] = tf32r(W2[i]);
    if (tid < HID) {
        sW3[tid] = tf32r(W3[tid]);
        sb1[tid] = b1[tid];
        sb2[tid] = b2[tid];
    }
    for (int i = tid; i < CC; i += 256) sbg[i] = bg[i];
    __syncthreads();

    const int warp = tid >> 5, lane = tid & 31;
    const float b3v = b3[0];

    const int i = blockIdx.x * 8 + warp;   // NN = 7500*8, always < NN

    const float di = g_dinv[i];
    const uint2* __restrict__ hb = (const uint2*)g_hb;  // 8B = 4 bf16 per lane

    auto h4at = [&](int row) -> float4 {
        uint2 v = hb[(size_t)row * 32 + lane];
        __nv_bfloat162 p0 = *(__nv_bfloat162*)&v.x;
        __nv_bfloat162 p1 = *(__nv_bfloat162*)&v.y;
        float2 f0 = __bfloat1622float2(p0);
        float2 f1 = __bfloat1622float2(p1);
        return make_float4(f0.x, f0.y, f1.x, f1.y);
    };

    // self loop
    float4 h = h4at(i);
    const float ws = di * di;
    float4 acc = make_float4(ws * h.x, ws * h.y, ws * h.z, ws * h.w);
    float4 acc2 = make_float4(0.f, 0.f, 0.f, 0.f);

    const int beg = g_offsets[i], end = g_offsets[i + 1];
    int e = beg;
    for (; e + 1 < end; e += 2) {
        int s0 = g_csr[e], s1 = g_csr[e + 1];
        float w0 = g_dinv[s0] * di, w1 = g_dinv[s1] * di;
        float4 h0 = h4at(s0);
        float4 h1 = h4at(s1);
        acc.x  = fmaf(w0, h0.x, acc.x);  acc.y  = fmaf(w0, h0.y, acc.y);
        acc.z  = fmaf(w0, h0.z, acc.z);  acc.w  = fmaf(w0, h0.w, acc.w);
        acc2.x = fmaf(w1, h1.x, acc2.x); acc2.y = fmaf(w1, h1.y, acc2.y);
        acc2.z = fmaf(w1, h1.z, acc2.z); acc2.w = fmaf(w1, h1.w, acc2.w);
    }
    if (e < end) {
        int s0 = g_csr[e];
        float w0 = g_dinv[s0] * di;
        float4 h0 = h4at(s0);
        acc.x = fmaf(w0, h0.x, acc.x); acc.y = fmaf(w0, h0.y, acc.y);
        acc.z = fmaf(w0, h0.z, acc.z); acc.w = fmaf(w0, h0.w, acc.w);
    }
    acc.x += acc2.x; acc.y += acc2.y; acc.z += acc2.z; acc.w += acc2.w;

    // x = relu(acc + bg) + state, tf32-rounded as next matmul operand
    float4 bgv = ((const float4*)sbg)[lane];
    float4 st = ((const float4*)(state + (size_t)i * CC))[lane];
    sx[warp][lane * 4 + 0] = tf32r(fmaxf(acc.x + bgv.x, 0.f) + st.x);
    sx[warp][lane * 4 + 1] = tf32r(fmaxf(acc.y + bgv.y, 0.f) + st.y);
    sx[warp][lane * 4 + 2] = tf32r(fmaxf(acc.z + bgv.z, 0.f) + st.z);
    sx[warp][lane * 4 + 3] = tf32r(fmaxf(acc.w + bgv.w, 0.f) + st.w);
    __syncwarp();

    // layer1: lane j computes y[j]
    float y = sb1[lane];
    #pragma unroll
    for (int c = 0; c < CC; c += 4) {
        float4 x4 = *(const float4*)&sx[warp][c];
        y = fmaf(x4.x, sW1[(c + 0) * HID + lane], y);
        y = fmaf(x4.y, sW1[(c + 1) * HID + lane], y);
        y = fmaf(x4.z, sW1[(c + 2) * HID + lane], y);
        y = fmaf(x4.w, sW1[(c + 3) * HID + lane], y);
    }
    y = tf32r((y > 0.f) ? y : 0.01f * y);

    // layer2 via shuffle broadcast
    float z = sb2[lane];
    #pragma unroll
    for (int k = 0; k < HID; k++) {
        float yk = __shfl_sync(0xffffffffu, y, k);
        z = fmaf(yk, sW2[k * HID + lane], z);
    }
    z = tf32r((z > 0.f) ? z : 0.01f * z);

    // layer3: dot + softplus
    float t = z * sW3[lane];
    #pragma unroll
    for (int o = 16; o; o >>= 1) t += __shfl_xor_sync(0xffffffffu, t, o);
    float conc = 0.f;
    if (lane == 0) {
        float v = t + b3v;
        conc = fmaxf(v, 0.f) + log1pf(expf(-fabsf(v)));
        g_conc[i] = conc;
        spart[warp] = conc;
    }
    __syncthreads();
    // block partial sum -> global
    if (tid == 0) {
        float a = 0.f;
        #pragma unroll
        for (int w = 0; w < 8; w++) a += spart[w];
        atomicAdd(&g_sum, a);
    }
}

// ---------------- K6: normalize -> d_out ----------------
__global__ void k_scale(float* __restrict__ out) {
    const float inv = 1.0f / (g_sum + 1e-20f);
    for (int i = blockIdx.x * blockDim.x + threadIdx.x; i < NN;
         i += gridDim.x * blockDim.x)
        out[i] = g_conc[i] * inv;
}

// ---------------- launch ----------------
extern "C" void kernel_launch(void* const* d_in, const int* in_sizes, int n_in,
                              void* d_out, int out_size) {
    const float* state = (const float*)d_in[0];
    const float* Wg    = (const float*)d_in[1];
    const float* bg    = (const float*)d_in[2];
    const float* W1    = (const float*)d_in[3];
    const float* b1    = (const float*)d_in[4];
    const float* W2    = (const float*)d_in[5];
    const float* b2    = (const float*)d_in[6];
    const float* W3    = (const float*)d_in[7];
    const float* b3    = (const float*)d_in[8];
    const void*  edge  = d_in[9];
    float* out = (float*)d_out;

    k_init<<<128, 256>>>(edge);
    k_hist<<<512, 256>>>(edge);
    k_scan<<<1, 1024>>>();
    k_fill<<<(EE + 255) / 256, 256>>>();
    k_gemm<<<(NN + 127) / 128, 256>>>(state, Wg);
    k_agg_mlp<<<NN / 8, 256>>>(state, bg, W1, b1, W2, b2, W3, b3);
    k_scale<<<(NN + 255) / 256, 256>>>(out);
}

// round 17
// speedup vs baseline: 1.6872x; 1.6872x over previous
#include <cuda_runtime.h>
#include <cuda_bf16.h>
#include <cstdint>

#define NN 60000
#define CC 128
#define EE 600000
#define HID 32

// TF32 operand rounding (round-to-nearest)
__device__ __forceinline__ float tf32r(float x) {
    uint32_t u;
    asm("cvt.rna.tf32.f32 %0, %1;" : "=r"(u) : "f"(x));
    return __uint_as_float(u);
}

// ---------------- scratch (__device__ globals; no allocations) ----------------
__device__ __nv_bfloat162 g_hb[(size_t)NN * (CC / 2)];  // state @ Wg, bf16
__device__ int   g_counts[NN];             // in-degree (edges only)
__device__ int   g_offsets[NN + 1];        // CSR offsets by dst
__device__ int   g_cursor[NN];
__device__ float g_dinv[NN];               // 1/sqrt(deg+1)
__device__ int   g_src32[EE];
__device__ int   g_dst32[EE];
__device__ int   g_csr[EE];                // src per CSR slot
__device__ float g_conc[NN];
__device__ float g_sum;
__device__ int   g_is64;
__device__ int   g_bsums[64];

// ---------------- K0: init (dtype detect, zero counts + sum) ----------------
__global__ void k_init(const void* edge) {
    int i = blockIdx.x * blockDim.x + threadIdx.x;
    if (i == 0) {
        const unsigned* w = (const unsigned*)edge;
        int is64 = 1;
        for (int k = 0; k < 32; k++) {
            if (w[2 * k + 1] != 0u) { is64 = 0; break; }
        }
        g_is64 = is64;
        g_sum = 0.0f;
    }
    for (int j = i; j < NN; j += gridDim.x * blockDim.x) g_counts[j] = 0;
}

// ---------------- K1: convert indices + dst histogram ----------------
__global__ void k_hist(const void* edge) {
    const int is64 = g_is64;
    for (int e = blockIdx.x * blockDim.x + threadIdx.x; e < EE;
         e += gridDim.x * blockDim.x) {
        int s, d;
        if (is64) {
            const long long* p = (const long long*)edge;
            s = (int)p[e]; d = (int)p[(size_t)EE + e];
        } else {
            const int* p = (const int*)edge;
            s = p[e]; d = p[(size_t)EE + e];
        }
        if ((unsigned)s >= NN) s = 0;   // safety clamp
        if ((unsigned)d >= NN) d = 0;
        g_src32[e] = s;
        g_dst32[e] = d;
        atomicAdd(&g_counts[d], 1);
    }
}

// ---------------- K2a: per-chunk COALESCED exclusive scan (+ dinv) -----------
__global__ __launch_bounds__(1024) void k_scan_block() {
    __shared__ int ss[1024];
    const int tid = threadIdx.x;
    const int i = blockIdx.x * 1024 + tid;          // coalesced
    int v = (i < NN) ? g_counts[i] : 0;
    ss[tid] = v;
    __syncthreads();
    for (int o = 1; o < 1024; o <<= 1) {
        int t = (tid >= o) ? ss[tid - o] : 0;
        __syncthreads();
        ss[tid] += t;
        __syncthreads();
    }
    int incl = ss[tid];
    if (i < NN) {
        g_offsets[i] = incl - v;                    // chunk-local exclusive
        g_dinv[i] = rsqrtf((float)(v + 1));         // +1 self loop
    }
    if (tid == 1023) g_bsums[blockIdx.x] = incl;
}

// ---------------- K2b: add chunk prefix (computed in-block), init cursors ----
__global__ __launch_bounds__(1024) void k_scan_add() {
    __shared__ int swarp[2];
    __shared__ int spref;
    const int tid = threadIdx.x;
    const int b = blockIdx.x;
    if (tid < 64) {
        int v = (tid < b) ? g_bsums[tid] : 0;       // b <= 58 < 64
        #pragma unroll
        for (int o = 16; o; o >>= 1) v += __shfl_xor_sync(0xffffffffu, v, o);
        if ((tid & 31) == 0) swarp[tid >> 5] = v;
    }
    __syncthreads();
    if (tid == 0) {
        spref = swarp[0] + swarp[1];
        if (b == 0) g_offsets[NN] = EE;             // indices clamped => total==EE
    }
    __syncthreads();
    const int pref = spref;
    const int i = b * 1024 + tid;                   // coalesced
    if (i < NN) {
        int off = g_offsets[i] + pref;
        g_offsets[i] = off;
        g_cursor[i] = off;
    }
}

// ---------------- K3: scatter edges into CSR ----------------
__global__ void k_fill() {
    for (int e = blockIdx.x * blockDim.x + threadIdx.x; e < EE;
         e += gridDim.x * blockDim.x) {
        int d = g_dst32[e];
        int pos = atomicAdd(&g_cursor[d], 1);
        g_csr[pos] = g_src32[e];
    }
}

// ---------------- K4: SGEMM  g_hb = bf16(state @ Wg) ----------------
__global__ __launch_bounds__(256) void k_gemm(const float* __restrict__ A,
                                              const float* __restrict__ B) {
    __shared__ float sA[2][8][132];   // [k][row], padded
    __shared__ float sB[2][8][128];   // [k][col]
    const int tid = threadIdx.x;
    const int tx = tid & 15, ty = tid >> 4;        // 16x16 thread grid, 8x8 tiles
    const int row0 = blockIdx.x * 128;
    const int lr = tid >> 1, lk4 = (tid & 1) * 4;  // A load mapping
    const int bk = tid >> 5, bn4 = tid & 31;       // B load mapping

    float acc[8][8];
    #pragma unroll
    for (int i = 0; i < 8; i++)
        #pragma unroll
        for (int j = 0; j < 8; j++) acc[i][j] = 0.f;

    auto load = [&](int buf, int kc) {
        float4 va = make_float4(0.f, 0.f, 0.f, 0.f);
        int r = row0 + lr;
        if (r < NN) va = *(const float4*)(A + (size_t)r * CC + kc * 8 + lk4);
        sA[buf][lk4 + 0][lr] = tf32r(va.x);
        sA[buf][lk4 + 1][lr] = tf32r(va.y);
        sA[buf][lk4 + 2][lr] = tf32r(va.z);
        sA[buf][lk4 + 3][lr] = tf32r(va.w);
        float4 vb = *(const float4*)(B + (size_t)(kc * 8 + bk) * CC + bn4 * 4);
        sB[buf][bk][bn4 * 4 + 0] = tf32r(vb.x);
        sB[buf][bk][bn4 * 4 + 1] = tf32r(vb.y);
        sB[buf][bk][bn4 * 4 + 2] = tf32r(vb.z);
        sB[buf][bk][bn4 * 4 + 3] = tf32r(vb.w);
    };

    load(0, 0);
    __syncthreads();

    #pragma unroll
    for (int kc = 0; kc < 16; kc++) {
        const int buf = kc & 1;
        if (kc < 15) load(buf ^ 1, kc + 1);
        #pragma unroll
        for (int k = 0; k < 8; k++) {
            float4 a0 = *(const float4*)&sA[buf][k][ty * 8];
            float4 a1 = *(const float4*)&sA[buf][k][ty * 8 + 4];
            float4 b0 = *(const float4*)&sB[buf][k][tx * 8];
            float4 b1 = *(const float4*)&sB[buf][k][tx * 8 + 4];
            float av[8] = {a0.x, a0.y, a0.z, a0.w, a1.x, a1.y, a1.z, a1.w};
            float bv[8] = {b0.x, b0.y, b0.z, b0.w, b1.x, b1.y, b1.z, b1.w};
            #pragma unroll
            for (int i = 0; i < 8; i++)
                #pragma unroll
                for (int j = 0; j < 8; j++)
                    acc[i][j] = fmaf(av[i], bv[j], acc[i][j]);
        }
        __syncthreads();
    }

    // epilogue: 8 fp32 -> 4 bf162 per row slice, one 16B store
    #pragma unroll
    for (int i = 0; i < 8; i++) {
        int r = row0 + ty * 8 + i;
        if (r < NN) {
            __nv_bfloat162 p0 = __floats2bfloat162_rn(acc[i][0], acc[i][1]);
            __nv_bfloat162 p1 = __floats2bfloat162_rn(acc[i][2], acc[i][3]);
            __nv_bfloat162 p2 = __floats2bfloat162_rn(acc[i][4], acc[i][5]);
            __nv_bfloat162 p3 = __floats2bfloat162_rn(acc[i][6], acc[i][7]);
            uint4 o;
            o.x = *(unsigned*)&p0; o.y = *(unsigned*)&p1;
            o.z = *(unsigned*)&p2; o.w = *(unsigned*)&p3;
            *(uint4*)(g_hb + (size_t)r * (CC / 2) + tx * 4) = o;
        }
    }
}

// ---------------- K5: warp-per-node gather + fused MLP + partial reduce ------
__global__ __launch_bounds__(256) void k_agg_mlp(
    const float* __restrict__ state, const float* __restrict__ bg,
    const float* __restrict__ W1, const float* __restrict__ b1,
    const float* __restrict__ W2, const float* __restrict__ b2,
    const float* __restrict__ W3, const float* __restrict__ b3) {
    __shared__ float sW1[CC * HID];    // [c][j], tf32-rounded
    __shared__ float sW2[HID * HID];   // [k][j], tf32-rounded
    __shared__ float sW3[HID];
    __shared__ float sb1[HID], sb2[HID];
    __shared__ float sbg[CC];
    __shared__ float sx[8][CC];
    __shared__ float spart[8];

    const int tid = threadIdx.x;
    for (int i = tid; i < CC * HID; i += 256) sW1[i] = tf32r(W1[i]);
    for (int i = tid; i < HID * HID; i += 256) sW2[i] = tf32r(W2[i]);
    if (tid < HID) {
        sW3[tid] = tf32r(W3[tid]);
        sb1[tid] = b1[tid];
        sb2[tid] = b2[tid];
    }
    for (int i = tid; i < CC; i += 256) sbg[i] = bg[i];
    __syncthreads();

    const int warp = tid >> 5, lane = tid & 31;
    const float b3v = b3[0];

    const int i = blockIdx.x * 8 + warp;   // NN = 7500*8, always < NN

    const float di = g_dinv[i];
    const uint2* __restrict__ hb = (const uint2*)g_hb;  // 8B = 4 bf16 per lane

    auto h4at = [&](int row) -> float4 {
        uint2 v = hb[(size_t)row * 32 + lane];
        __nv_bfloat162 p0 = *(__nv_bfloat162*)&v.x;
        __nv_bfloat162 p1 = *(__nv_bfloat162*)&v.y;
        float2 f0 = __bfloat1622float2(p0);
        float2 f1 = __bfloat1622float2(p1);
        return make_float4(f0.x, f0.y, f1.x, f1.y);
    };

    // self loop
    float4 h = h4at(i);
    const float ws = di * di;
    float4 acc = make_float4(ws * h.x, ws * h.y, ws * h.z, ws * h.w);
    float4 acc2 = make_float4(0.f, 0.f, 0.f, 0.f);

    const int beg = g_offsets[i], end = g_offsets[i + 1];
    int e = beg;
    for (; e + 1 < end; e += 2) {
        int s0 = g_csr[e], s1 = g_csr[e + 1];
        float w0 = g_dinv[s0] * di, w1 = g_dinv[s1] * di;
        float4 h0 = h4at(s0);
        float4 h1 = h4at(s1);
        acc.x  = fmaf(w0, h0.x, acc.x);  acc.y  = fmaf(w0, h0.y, acc.y);
        acc.z  = fmaf(w0, h0.z, acc.z);  acc.w  = fmaf(w0, h0.w, acc.w);
        acc2.x = fmaf(w1, h1.x, acc2.x); acc2.y = fmaf(w1, h1.y, acc2.y);
        acc2.z = fmaf(w1, h1.z, acc2.z); acc2.w = fmaf(w1, h1.w, acc2.w);
    }
    if (e < end) {
        int s0 = g_csr[e];
        float w0 = g_dinv[s0] * di;
        float4 h0 = h4at(s0);
        acc.x = fmaf(w0, h0.x, acc.x); acc.y = fmaf(w0, h0.y, acc.y);
        acc.z = fmaf(w0, h0.z, acc.z); acc.w = fmaf(w0, h0.w, acc.w);
    }
    acc.x += acc2.x; acc.y += acc2.y; acc.z += acc2.z; acc.w += acc2.w;

    // x = relu(acc + bg) + state, tf32-rounded as next matmul operand
    float4 bgv = ((const float4*)sbg)[lane];
    float4 st = ((const float4*)(state + (size_t)i * CC))[lane];
    sx[warp][lane * 4 + 0] = tf32r(fmaxf(acc.x + bgv.x, 0.f) + st.x);
    sx[warp][lane * 4 + 1] = tf32r(fmaxf(acc.y + bgv.y, 0.f) + st.y);
    sx[warp][lane * 4 + 2] = tf32r(fmaxf(acc.z + bgv.z, 0.f) + st.z);
    sx[warp][lane * 4 + 3] = tf32r(fmaxf(acc.w + bgv.w, 0.f) + st.w);
    __syncwarp();

    // layer1: lane j computes y[j]
    float y = sb1[lane];
    #pragma unroll
    for (int c = 0; c < CC; c += 4) {
        float4 x4 = *(const float4*)&sx[warp][c];
        y = fmaf(x4.x, sW1[(c + 0) * HID + lane], y);
        y = fmaf(x4.y, sW1[(c + 1) * HID + lane], y);
        y = fmaf(x4.z, sW1[(c + 2) * HID + lane], y);
        y = fmaf(x4.w, sW1[(c + 3) * HID + lane], y);
    }
    y = tf32r((y > 0.f) ? y : 0.01f * y);

    // layer2 via shuffle broadcast
    float z = sb2[lane];
    #pragma unroll
    for (int k = 0; k < HID; k++) {
        float yk = __shfl_sync(0xffffffffu, y, k);
        z = fmaf(yk, sW2[k * HID + lane], z);
    }
    z = tf32r((z > 0.f) ? z : 0.01f * z);

    // layer3: dot + softplus
    float t = z * sW3[lane];
    #pragma unroll
    for (int o = 16; o; o >>= 1) t += __shfl_xor_sync(0xffffffffu, t, o);
    float conc = 0.f;
    if (lane == 0) {
        float v = t + b3v;
        conc = fmaxf(v, 0.f) + log1pf(expf(-fabsf(v)));
        g_conc[i] = conc;
        spart[warp] = conc;
    }
    __syncthreads();
    // block partial sum -> global
    if (tid == 0) {
        float a = 0.f;
        #pragma unroll
        for (int w = 0; w < 8; w++) a += spart[w];
        atomicAdd(&g_sum, a);
    }
}

// ---------------- K6: normalize -> d_out ----------------
__global__ void k_scale(float* __restrict__ out) {
    const float inv = 1.0f / (g_sum + 1e-20f);
    for (int i = blockIdx.x * blockDim.x + threadIdx.x; i < NN;
         i += gridDim.x * blockDim.x)
        out[i] = g_conc[i] * inv;
}

// ---------------- launch ----------------
extern "C" void kernel_launch(void* const* d_in, const int* in_sizes, int n_in,
                              void* d_out, int out_size) {
    const float* state = (const float*)d_in[0];
    const float* Wg    = (const float*)d_in[1];
    const float* bg    = (const float*)d_in[2];
    const float* W1    = (const float*)d_in[3];
    const float* b1    = (const float*)d_in[4];
    const float* W2    = (const float*)d_in[5];
    const float* b2    = (const float*)d_in[6];
    const float* W3    = (const float*)d_in[7];
    const float* b3    = (const float*)d_in[8];
    const void*  edge  = d_in[9];
    float* out = (float*)d_out;

    const int NB = (NN + 1023) / 1024;   // 59 scan chunks

    k_init<<<128, 256>>>(edge);
    k_hist<<<512, 256>>>(edge);
    k_scan_block<<<NB, 1024>>>();
    k_scan_add<<<NB, 1024>>>();
    k_fill<<<(EE + 255) / 256, 256>>>();
    k_gemm<<<(NN + 127) / 128, 256>>>(state, Wg);
    k_agg_mlp<<<NN / 8, 256>>>(state, bg, W1, b1, W2, b2, W3, b3);
    k_scale<<<(NN + 255) / 256, 256>>>(out);
}